// round 3
// baseline (speedup 1.0000x reference)
#include <cuda_runtime.h>
#include <math.h>

// Problem constants (fixed shapes from reference)
constexpr int Bb = 8;
constexpr int Cc = 1024;
constexpr int Nn = 64;
constexpr int Pp = 32;
constexpr int SS = Nn * Pp;        // 2048 spatial per batch
constexpr int AT = Bb * SS;        // 16384 tokens
constexpr int Ee = 3;
constexpr int Hh = 4096;
constexpr int Oo = 1024;

// Scratch (device globals: allocation-free per harness rules)
__device__ float g_xt[(size_t)AT * Cc];     // 64 MB  tokens [A, C]
__device__ float g_h [(size_t)AT * Hh];     // 256 MB expert hidden [A, H]
__device__ float g_gates[AT * Ee];          // [A, E]

// ---------------------------------------------------------------------------
// 1) Transpose x [B, C, S] -> xt [B, S, C]  (S = N*P)
// ---------------------------------------------------------------------------
__global__ void transpose_kernel(const float* __restrict__ x) {
    __shared__ float tile[32][33];
    int s0 = blockIdx.x * 32;
    int c0 = blockIdx.y * 32;
    int b  = blockIdx.z;
    int tx = threadIdx.x, ty = threadIdx.y;   // 32 x 8

    const float* xp = x + (size_t)b * Cc * SS;
#pragma unroll
    for (int i = 0; i < 32; i += 8)
        tile[ty + i][tx] = xp[(size_t)(c0 + ty + i) * SS + s0 + tx];
    __syncthreads();

    float* xtp = g_xt + (size_t)b * SS * Cc;
#pragma unroll
    for (int i = 0; i < 32; i += 8)
        xtp[(size_t)(s0 + ty + i) * Cc + c0 + tx] = tile[tx][ty + i];
}

// ---------------------------------------------------------------------------
// 2) Noisy top-2 router -> gates [A, 3]
// ---------------------------------------------------------------------------
__global__ void router_kernel(const float* __restrict__ Wg, const float* __restrict__ bg,
                              const float* __restrict__ Wn, const float* __restrict__ bn,
                              const float* __restrict__ noise_u) {
    __shared__ float sWg[Cc * Ee];
    __shared__ float sWn[Cc * Ee];
    int tid = threadIdx.x;
    for (int i = tid; i < Cc * Ee; i += blockDim.x) {
        sWg[i] = Wg[i];
        sWn[i] = Wn[i];
    }
    __syncthreads();

    int warp = tid >> 5, lane = tid & 31;
    int a = blockIdx.x * 8 + warp;

    float acc[6] = {0.f, 0.f, 0.f, 0.f, 0.f, 0.f};
    const float* xr = g_xt + (size_t)a * Cc;
    for (int c = lane; c < Cc; c += 32) {
        float xv = xr[c];
#pragma unroll
        for (int e = 0; e < 3; e++) {
            acc[e]     = fmaf(xv, sWg[c * 3 + e], acc[e]);
            acc[3 + e] = fmaf(xv, sWn[c * 3 + e], acc[3 + e]);
        }
    }
#pragma unroll
    for (int k = 0; k < 6; k++)
#pragma unroll
        for (int off = 16; off > 0; off >>= 1)
            acc[k] += __shfl_xor_sync(0xffffffffu, acc[k], off);

    if (lane == 0) {
        float gl[3], nl[3];
#pragma unroll
        for (int e = 0; e < 3; e++) {
            gl[e] = acc[e] + bg[e];
            nl[e] = acc[3 + e] + bn[e];
        }
        // softmax over noise logits
        float m = fmaxf(nl[0], fmaxf(nl[1], nl[2]));
        float ex0 = expf(nl[0] - m), ex1 = expf(nl[1] - m), ex2 = expf(nl[2] - m);
        float inv = 1.f / (ex0 + ex1 + ex2);
        float lo[3];
        lo[0] = gl[0] + noise_u[a * 3 + 0] * ex0 * inv;
        lo[1] = gl[1] + noise_u[a * 3 + 1] * ex1 * inv;
        lo[2] = gl[2] + noise_u[a * 3 + 2] * ex2 * inv;
        // drop the min (<= scan matches jax top_k tie order: keep earliest equal)
        int imin = 0;
        if (lo[1] <= lo[imin]) imin = 1;
        if (lo[2] <= lo[imin]) imin = 2;
        float m2 = -INFINITY;
#pragma unroll
        for (int e = 0; e < 3; e++)
            if (e != imin) m2 = fmaxf(m2, lo[e]);
        float g[3], s = 0.f;
#pragma unroll
        for (int e = 0; e < 3; e++) {
            g[e] = (e == imin) ? 0.f : expf(lo[e] - m2);
            s += g[e];
        }
        float invs = 1.f / s;
#pragma unroll
        for (int e = 0; e < 3; e++)
            g_gates[a * 3 + e] = g[e] * invs;
    }
}

// ---------------------------------------------------------------------------
// 3) Tiled SGEMM 128x128x16, 256 threads, 8x8 microtile, reg-prefetch
//    MODE 0: A = g_xt [AT x KD], B = W1e, epilogue GELU -> g_h
//    MODE 1: A = g_h  [AT x KD], B = W2e, epilogue gate*(.+b2) -> permuted out
// ---------------------------------------------------------------------------
__device__ __forceinline__ float gelu_exact(float v) {
    return 0.5f * v * (1.f + erff(v * 0.70710678118654752440f));
}

template <int KD, int ND, int MODE>
__global__ void __launch_bounds__(256)
sgemm_kernel(const float* __restrict__ Bp, const float* __restrict__ bias,
             float* __restrict__ outp, int e, int accflag) {
    constexpr int BM = 128, BN = 128, BK = 16;
    __shared__ float As[BK][BM];
    __shared__ float Bs[BK][BN];

    const float* Ap = (MODE == 0) ? g_xt : g_h;

    int tid = threadIdx.x;
    int m0 = blockIdx.y * BM;
    int n0 = blockIdx.x * BN;

    int arow = tid >> 2;            // 0..63
    int acol = (tid & 3) << 2;      // 0,4,8,12
    int brow = tid >> 5;            // 0..7
    int bcol = (tid & 31) << 2;     // 0..124

    const float* Ab0 = Ap + (size_t)(m0 + arow) * KD + acol;
    const float* Ab1 = Ap + (size_t)(m0 + arow + 64) * KD + acol;
    const float* Bb0 = Bp + (size_t)brow * ND + n0 + bcol;
    const float* Bb1 = Bp + (size_t)(brow + 8) * ND + n0 + bcol;

    float4 ra0 = *(const float4*)(Ab0);
    float4 ra1 = *(const float4*)(Ab1);
    float4 rb0 = *(const float4*)(Bb0);
    float4 rb1 = *(const float4*)(Bb1);

    int tx = tid & 15, ty = tid >> 4;
    float acc[8][8];
#pragma unroll
    for (int i = 0; i < 8; i++)
#pragma unroll
        for (int j = 0; j < 8; j++) acc[i][j] = 0.f;

    constexpr int NT = KD / BK;
    for (int t = 0; t < NT; ++t) {
        // commit prefetched tile to smem
        As[acol + 0][arow] = ra0.x; As[acol + 1][arow] = ra0.y;
        As[acol + 2][arow] = ra0.z; As[acol + 3][arow] = ra0.w;
        As[acol + 0][arow + 64] = ra1.x; As[acol + 1][arow + 64] = ra1.y;
        As[acol + 2][arow + 64] = ra1.z; As[acol + 3][arow + 64] = ra1.w;
        *(float4*)&Bs[brow][bcol]     = rb0;
        *(float4*)&Bs[brow + 8][bcol] = rb1;
        __syncthreads();

        if (t + 1 < NT) {
            ra0 = *(const float4*)(Ab0 + (t + 1) * BK);
            ra1 = *(const float4*)(Ab1 + (t + 1) * BK);
            rb0 = *(const float4*)(Bb0 + (size_t)(t + 1) * BK * ND);
            rb1 = *(const float4*)(Bb1 + (size_t)(t + 1) * BK * ND);
        }

#pragma unroll
        for (int kk = 0; kk < BK; ++kk) {
            float af[8], bf[8];
            *(float4*)(af)     = *(const float4*)&As[kk][ty * 8];
            *(float4*)(af + 4) = *(const float4*)&As[kk][ty * 8 + 4];
            *(float4*)(bf)     = *(const float4*)&Bs[kk][tx * 8];
            *(float4*)(bf + 4) = *(const float4*)&Bs[kk][tx * 8 + 4];
#pragma unroll
            for (int i = 0; i < 8; i++)
#pragma unroll
                for (int j = 0; j < 8; j++)
                    acc[i][j] = fmaf(af[i], bf[j], acc[i][j]);
        }
        __syncthreads();
    }

    if (MODE == 0) {
        // GELU epilogue -> g_h [AT x ND]
#pragma unroll
        for (int i = 0; i < 8; i++) {
            int m = m0 + ty * 8 + i;
            float* hr = g_h + (size_t)m * ND + n0 + tx * 8;
            float v[8];
#pragma unroll
            for (int j = 0; j < 8; j++) {
                int n = n0 + tx * 8 + j;
                v[j] = gelu_exact(acc[i][j] + bias[n]);
            }
            *(float4*)(hr)     = make_float4(v[0], v[1], v[2], v[3]);
            *(float4*)(hr + 4) = make_float4(v[4], v[5], v[6], v[7]);
        }
    } else {
        // gate * (acc + b2) scattered to out[B, O, N, P]; p is contiguous in m
        int mbase = m0 + ty * 8;
        int p  = mbase & 31;
        int nn = (mbase >> 5) & 63;
        int bb = mbase >> 11;
        float gate[8];
#pragma unroll
        for (int i = 0; i < 8; i++)
            gate[i] = g_gates[(mbase + i) * 3 + e];
#pragma unroll
        for (int j = 0; j < 8; j++) {
            int n = n0 + tx * 8 + j;
            float bv = bias[n];
            size_t idx0 = (((size_t)bb * Oo + n) * Nn + nn) * Pp + p;
            float v[8];
#pragma unroll
            for (int i = 0; i < 8; i++)
                v[i] = gate[i] * (acc[i][j] + bv);
            if (accflag) {
                float4 o0 = *(float4*)&outp[idx0];
                float4 o1 = *(float4*)&outp[idx0 + 4];
                o0.x += v[0]; o0.y += v[1]; o0.z += v[2]; o0.w += v[3];
                o1.x += v[4]; o1.y += v[5]; o1.z += v[6]; o1.w += v[7];
                *(float4*)&outp[idx0]     = o0;
                *(float4*)&outp[idx0 + 4] = o1;
            } else {
                *(float4*)&outp[idx0]     = make_float4(v[0], v[1], v[2], v[3]);
                *(float4*)&outp[idx0 + 4] = make_float4(v[4], v[5], v[6], v[7]);
            }
        }
    }
}

// ---------------------------------------------------------------------------
// Launcher (graph-capturable: kernel launches only)
// ---------------------------------------------------------------------------
extern "C" void kernel_launch(void* const* d_in, const int* in_sizes, int n_in,
                              void* d_out, int out_size) {
    (void)in_sizes; (void)n_in; (void)out_size;
    const float* x       = (const float*)d_in[0];
    const float* Wg      = (const float*)d_in[1];
    const float* bg      = (const float*)d_in[2];
    const float* Wn      = (const float*)d_in[3];
    const float* bn      = (const float*)d_in[4];
    const float* W1      = (const float*)d_in[5];
    const float* b1      = (const float*)d_in[6];
    const float* W2      = (const float*)d_in[7];
    const float* b2      = (const float*)d_in[8];
    const float* noise_u = (const float*)d_in[9];
    float* out = (float*)d_out;

    transpose_kernel<<<dim3(SS / 32, Cc / 32, Bb), dim3(32, 8)>>>(x);
    router_kernel<<<AT / 8, 256>>>(Wg, bg, Wn, bn, noise_u);

    for (int e = 0; e < Ee; e++) {
        sgemm_kernel<Cc, Hh, 0><<<dim3(Hh / 128, AT / 128), 256>>>(
            W1 + (size_t)e * Cc * Hh, b1 + (size_t)e * Hh, nullptr, e, 0);
        sgemm_kernel<Hh, Oo, 1><<<dim3(Oo / 128, AT / 128), 256>>>(
            W2 + (size_t)e * Hh * Oo, b2 + (size_t)e * Oo, out, e, (e > 0) ? 1 : 0);
    }
}

// round 6
// speedup vs baseline: 2.0358x; 2.0358x over previous
#include <cuda_runtime.h>
#include <cuda_bf16.h>
#include <math.h>
#include <stdint.h>

// Problem constants
constexpr int Bb = 8;
constexpr int Cc = 1024;
constexpr int Nn = 64;
constexpr int Pp = 32;
constexpr int SS = Nn * Pp;        // 2048
constexpr int AT = Bb * SS;        // 16384 tokens
constexpr int Ee = 3;
constexpr int Hh = 4096;
constexpr int Oo = 1024;

// Device scratch (allocation-free per harness rules)
__device__ float          g_xt [(size_t)AT * Cc];
__device__ __nv_bfloat16  g_xhi[(size_t)AT * Cc];
__device__ __nv_bfloat16  g_xlo[(size_t)AT * Cc];
__device__ __nv_bfloat16  g_hhi[(size_t)AT * Hh];
__device__ __nv_bfloat16  g_hlo[(size_t)AT * Hh];
__device__ __nv_bfloat16  g_w1hi[(size_t)Ee * Hh * Cc];   // W1^T [E][H][C]
__device__ __nv_bfloat16  g_w1lo[(size_t)Ee * Hh * Cc];
__device__ __nv_bfloat16  g_w2hi[(size_t)Ee * Oo * Hh];   // W2^T [E][O][H]
__device__ __nv_bfloat16  g_w2lo[(size_t)Ee * Oo * Hh];
__device__ float          g_gates[AT * Ee];

// ---------------------------------------------------------------------------
// PTX helpers (all sm_80+ baseline ISA — compiles at plain sm_100)
// ---------------------------------------------------------------------------
__device__ __forceinline__ uint32_t smem_u32(const void* p) {
    uint32_t r;
    asm("{ .reg .u64 t; cvta.to.shared.u64 t, %1; cvt.u32.u64 %0, t; }"
        : "=r"(r) : "l"(p));
    return r;
}
__device__ __forceinline__ void cp16(uint32_t dst, const void* src) {
    asm volatile("cp.async.cg.shared.global [%0], [%1], 16;" :: "r"(dst), "l"(src));
}
#define CP_COMMIT() asm volatile("cp.async.commit_group;" ::: "memory")
#define CP_WAIT(n)  asm volatile("cp.async.wait_group %0;" :: "n"(n) : "memory")

__device__ __forceinline__ void ldm4(uint32_t* r, uint32_t addr) {
    asm volatile("ldmatrix.sync.aligned.m8n8.x4.shared.b16 {%0,%1,%2,%3}, [%4];"
                 : "=r"(r[0]), "=r"(r[1]), "=r"(r[2]), "=r"(r[3]) : "r"(addr));
}
__device__ __forceinline__ void mma16816(float* d, const uint32_t* a, const uint32_t* b) {
    asm volatile(
        "mma.sync.aligned.m16n8k16.row.col.f32.bf16.bf16.f32 "
        "{%0,%1,%2,%3}, {%4,%5,%6,%7}, {%8,%9}, {%0,%1,%2,%3};"
        : "+f"(d[0]), "+f"(d[1]), "+f"(d[2]), "+f"(d[3])
        : "r"(a[0]), "r"(a[1]), "r"(a[2]), "r"(a[3]), "r"(b[0]), "r"(b[1]));
}
__device__ __forceinline__ float gelu_exact(float v) {
    return 0.5f * v * (1.f + erff(v * 0.70710678118654752440f));
}
__device__ __forceinline__ uint32_t pack_bf2(float a, float b) {
    __nv_bfloat162 p;
    p.x = __float2bfloat16(a);
    p.y = __float2bfloat16(b);
    return *(uint32_t*)&p;
}

// ---------------------------------------------------------------------------
// 1) Transpose x [B, C, S] -> g_xt fp32 [A, C] + bf16 hi/lo split
// ---------------------------------------------------------------------------
__global__ void transpose_kernel(const float* __restrict__ x) {
    __shared__ float tile[32][33];
    int s0 = blockIdx.x * 32, c0 = blockIdx.y * 32, b = blockIdx.z;
    int tx = threadIdx.x, ty = threadIdx.y;

    const float* xp = x + (size_t)b * Cc * SS;
#pragma unroll
    for (int i = 0; i < 32; i += 8)
        tile[ty + i][tx] = xp[(size_t)(c0 + ty + i) * SS + s0 + tx];
    __syncthreads();

    size_t abase = (size_t)b * SS;
#pragma unroll
    for (int i = 0; i < 32; i += 8) {
        float v = tile[tx][ty + i];
        size_t o = (abase + s0 + ty + i) * Cc + c0 + tx;
        g_xt[o] = v;
        __nv_bfloat16 hi = __float2bfloat16(v);
        g_xhi[o] = hi;
        g_xlo[o] = __float2bfloat16(v - __bfloat162float(hi));
    }
}

// ---------------------------------------------------------------------------
// 2) Weight transpose + hi/lo split:  W [E, RK, CN] -> Wt [E, CN, RK] bf16
// ---------------------------------------------------------------------------
template <int WHICH>
__global__ void wsplit_kernel(const float* __restrict__ W) {
    constexpr int RK = (WHICH == 1) ? Cc : Hh;
    constexpr int CN = (WHICH == 1) ? Hh : Oo;
    __shared__ float tile[32][33];
    int n0 = blockIdx.x * 32, k0 = blockIdx.y * 32, e = blockIdx.z;
    int tx = threadIdx.x, ty = threadIdx.y;

    const float* Wp = W + (size_t)e * RK * CN;
#pragma unroll
    for (int i = 0; i < 32; i += 8)
        tile[ty + i][tx] = Wp[(size_t)(k0 + ty + i) * CN + n0 + tx];
    __syncthreads();

    __nv_bfloat16* oh = (WHICH == 1 ? g_w1hi : g_w2hi) + (size_t)e * CN * RK;
    __nv_bfloat16* ol = (WHICH == 1 ? g_w1lo : g_w2lo) + (size_t)e * CN * RK;
#pragma unroll
    for (int i = 0; i < 32; i += 8) {
        float v = tile[tx][ty + i];
        size_t o = (size_t)(n0 + ty + i) * RK + k0 + tx;
        __nv_bfloat16 hi = __float2bfloat16(v);
        oh[o] = hi;
        ol[o] = __float2bfloat16(v - __bfloat162float(hi));
    }
}

// ---------------------------------------------------------------------------
// 3) Noisy top-2 router (fp32 path, from the passing R3 kernel)
// ---------------------------------------------------------------------------
__global__ void router_kernel(const float* __restrict__ Wg, const float* __restrict__ bg,
                              const float* __restrict__ Wn, const float* __restrict__ bn,
                              const float* __restrict__ noise_u) {
    __shared__ float sWg[Cc * Ee];
    __shared__ float sWn[Cc * Ee];
    int tid = threadIdx.x;
    for (int i = tid; i < Cc * Ee; i += blockDim.x) {
        sWg[i] = Wg[i];
        sWn[i] = Wn[i];
    }
    __syncthreads();

    int warp = tid >> 5, lane = tid & 31;
    int a = blockIdx.x * 8 + warp;

    float acc[6] = {0.f, 0.f, 0.f, 0.f, 0.f, 0.f};
    const float* xr = g_xt + (size_t)a * Cc;
    for (int c = lane; c < Cc; c += 32) {
        float xv = xr[c];
#pragma unroll
        for (int e = 0; e < 3; e++) {
            acc[e]     = fmaf(xv, sWg[c * 3 + e], acc[e]);
            acc[3 + e] = fmaf(xv, sWn[c * 3 + e], acc[3 + e]);
        }
    }
#pragma unroll
    for (int k = 0; k < 6; k++)
#pragma unroll
        for (int off = 16; off > 0; off >>= 1)
            acc[k] += __shfl_xor_sync(0xffffffffu, acc[k], off);

    if (lane == 0) {
        float gl[3], nl[3];
#pragma unroll
        for (int e = 0; e < 3; e++) {
            gl[e] = acc[e] + bg[e];
            nl[e] = acc[3 + e] + bn[e];
        }
        float m = fmaxf(nl[0], fmaxf(nl[1], nl[2]));
        float ex0 = expf(nl[0] - m), ex1 = expf(nl[1] - m), ex2 = expf(nl[2] - m);
        float inv = 1.f / (ex0 + ex1 + ex2);
        float lo[3];
        lo[0] = gl[0] + noise_u[a * 3 + 0] * ex0 * inv;
        lo[1] = gl[1] + noise_u[a * 3 + 1] * ex1 * inv;
        lo[2] = gl[2] + noise_u[a * 3 + 2] * ex2 * inv;
        int imin = 0;
        if (lo[1] <= lo[imin]) imin = 1;
        if (lo[2] <= lo[imin]) imin = 2;
        float m2 = -INFINITY;
#pragma unroll
        for (int e = 0; e < 3; e++)
            if (e != imin) m2 = fmaxf(m2, lo[e]);
        float g[3], s = 0.f;
#pragma unroll
        for (int e = 0; e < 3; e++) {
            g[e] = (e == imin) ? 0.f : expf(lo[e] - m2);
            s += g[e];
        }
        float invs = 1.f / s;
#pragma unroll
        for (int e = 0; e < 3; e++)
            g_gates[a * 3 + e] = g[e] * invs;
    }
}

// ---------------------------------------------------------------------------
// 4) mma.sync GEMM: CTA 128x256, BK=32, bf16 hi/lo 3-MMA split, fp32 acc
//    8 warps (2 M x 4 N), warp tile 64x64. 3-stage cp.async pipeline.
//    Smem rows padded to 80B -> conflict-free ldmatrix.
//    MODE 0: A = x hi/lo,  B = W1t[e]; epilogue GELU -> h hi/lo
//    MODE 1: A = h hi/lo,  B = W2t[e]; epilogue gate*(.+b2) -> out scatter
// ---------------------------------------------------------------------------
constexpr int SG_A = 10240;                  // 128 rows * 80B, one split
constexpr int SG_B = 20480;                  // 256 rows * 80B, one split
constexpr int STAGE_BYTES = 2 * SG_A + 2 * SG_B;   // 61440
constexpr int SMEM_T = 3 * STAGE_BYTES;            // 184320

template <int KD, int ND, int MODE>
__global__ void __launch_bounds__(256, 1)
moe_gemm(const float* __restrict__ bias, float* __restrict__ outp, int e, int accflag) {
    constexpr int NT = KD / 32;
    extern __shared__ char smem[];
    const uint32_t sbase = smem_u32(smem);

    int tid = threadIdx.x, wid = tid >> 5, lane = tid & 31;
    int wm = wid >> 2, wn = wid & 3;              // warp grid 2 x 4
    int m0 = blockIdx.y * 128, n0 = blockIdx.x * 256;

    const __nv_bfloat16* Ah = (MODE == 0) ? g_xhi : g_hhi;
    const __nv_bfloat16* Al = (MODE == 0) ? g_xlo : g_hlo;
    const __nv_bfloat16* Bh = (MODE == 0) ? g_w1hi + (size_t)e * Hh * Cc
                                          : g_w2hi + (size_t)e * Oo * Hh;
    const __nv_bfloat16* Bl = (MODE == 0) ? g_w1lo + (size_t)e * Hh * Cc
                                          : g_w2lo + (size_t)e * Oo * Hh;
    const char* gA[2] = { (const char*)(Ah + (size_t)m0 * KD),
                          (const char*)(Al + (size_t)m0 * KD) };
    const char* gB[2] = { (const char*)(Bh + (size_t)n0 * KD),
                          (const char*)(Bl + (size_t)n0 * KD) };

    auto load_stage = [&](int t) {
        uint32_t sb = sbase + (t % 3) * STAGE_BYTES;
        size_t koff = (size_t)t * 64;            // 32 bf16 = 64B per chunk
#pragma unroll
        for (int sp = 0; sp < 2; sp++) {         // A: 128 rows x 4 chunks
            const char* g = gA[sp] + koff;
            uint32_t d = sb + sp * SG_A;
#pragma unroll
            for (int it = 0; it < 2; it++) {
                int ch = tid + it * 256;
                int r = ch >> 2, c = ch & 3;
                cp16(d + r * 80 + c * 16, g + (size_t)r * (KD * 2) + c * 16);
            }
        }
#pragma unroll
        for (int sp = 0; sp < 2; sp++) {         // B: 256 rows x 4 chunks
            const char* g = gB[sp] + koff;
            uint32_t d = sb + 2 * SG_A + sp * SG_B;
#pragma unroll
            for (int it = 0; it < 4; it++) {
                int ch = tid + it * 256;
                int r = ch >> 2, c = ch & 3;
                cp16(d + r * 80 + c * 16, g + (size_t)r * (KD * 2) + c * 16);
            }
        }
    };

    float acc[128];
#pragma unroll
    for (int i = 0; i < 128; i++) acc[i] = 0.f;

    // ldmatrix lane addressing (within a stage)
    const int a_r = lane & 15, a_k = (lane >> 4) * 16;
    const int b_r = (lane & 7) + ((lane >> 4) << 3), b_k = ((lane >> 3) & 1) * 16;

    load_stage(0); CP_COMMIT();
    load_stage(1); CP_COMMIT();

    for (int t = 0; t < NT; ++t) {
        if (t + 2 < NT)      { load_stage(t + 2); CP_COMMIT(); CP_WAIT(2); }
        else if (t + 1 < NT) { CP_WAIT(1); }
        else                 { CP_WAIT(0); }
        __syncthreads();

        uint32_t sb = sbase + (t % 3) * STAGE_BYTES;
        uint32_t sAh = sb, sAl = sb + SG_A;
        uint32_t sBh = sb + 2 * SG_A, sBl = sBh + SG_B;

#pragma unroll
        for (int k16 = 0; k16 < 2; ++k16) {
            int kb = k16 * 32;
            uint32_t ah[4][4], al[4][4], bh[4][4], bl[4][4];
#pragma unroll
            for (int mt = 0; mt < 4; mt++)
                ldm4(ah[mt], sAh + (wm * 64 + mt * 16 + a_r) * 80 + kb + a_k);
#pragma unroll
            for (int np = 0; np < 4; np++)
                ldm4(bh[np], sBh + (wn * 64 + np * 16 + b_r) * 80 + kb + b_k);
#pragma unroll
            for (int mt = 0; mt < 4; mt++)
#pragma unroll
                for (int nt = 0; nt < 8; nt++)
                    mma16816(acc + (mt * 8 + nt) * 4, ah[mt], &bh[nt >> 1][(nt & 1) * 2]);
#pragma unroll
            for (int mt = 0; mt < 4; mt++)
                ldm4(al[mt], sAl + (wm * 64 + mt * 16 + a_r) * 80 + kb + a_k);
#pragma unroll
            for (int mt = 0; mt < 4; mt++)
#pragma unroll
                for (int nt = 0; nt < 8; nt++)
                    mma16816(acc + (mt * 8 + nt) * 4, al[mt], &bh[nt >> 1][(nt & 1) * 2]);
#pragma unroll
            for (int np = 0; np < 4; np++)
                ldm4(bl[np], sBl + (wn * 64 + np * 16 + b_r) * 80 + kb + b_k);
#pragma unroll
            for (int mt = 0; mt < 4; mt++)
#pragma unroll
                for (int nt = 0; nt < 8; nt++)
                    mma16816(acc + (mt * 8 + nt) * 4, ah[mt], &bl[nt >> 1][(nt & 1) * 2]);
        }
        __syncthreads();
    }

    // ---- epilogue ----
    if (MODE == 0) {
#pragma unroll
        for (int mt = 0; mt < 4; mt++) {
            int row0 = m0 + wm * 64 + mt * 16 + (lane >> 2);
#pragma unroll
            for (int nt = 0; nt < 8; nt++) {
                const float* a = acc + (mt * 8 + nt) * 4;
                int col = n0 + wn * 64 + nt * 8 + (lane & 3) * 2;
                float b0 = __ldg(&bias[col]), b1 = __ldg(&bias[col + 1]);
                float v00 = gelu_exact(a[0] + b0), v01 = gelu_exact(a[1] + b1);
                float v10 = gelu_exact(a[2] + b0), v11 = gelu_exact(a[3] + b1);
                __nv_bfloat16 h00 = __float2bfloat16(v00), h01 = __float2bfloat16(v01);
                __nv_bfloat16 h10 = __float2bfloat16(v10), h11 = __float2bfloat16(v11);
                size_t o0 = (size_t)row0 * ND + col;
                size_t o1 = (size_t)(row0 + 8) * ND + col;
                __nv_bfloat162 p;
                p.x = h00; p.y = h01; *(uint32_t*)&g_hhi[o0] = *(uint32_t*)&p;
                p.x = h10; p.y = h11; *(uint32_t*)&g_hhi[o1] = *(uint32_t*)&p;
                *(uint32_t*)&g_hlo[o0] =
                    pack_bf2(v00 - __bfloat162float(h00), v01 - __bfloat162float(h01));
                *(uint32_t*)&g_hlo[o1] =
                    pack_bf2(v10 - __bfloat162float(h10), v11 - __bfloat162float(h11));
            }
        }
    } else {
        // gates for this CTA's 128 rows -> smem (pipeline smem is free now)
        float* sg = (float*)smem;
        if (tid < 128) sg[tid] = g_gates[(m0 + tid) * 3 + e];
        __syncthreads();
        float* buf = (float*)(smem + 512) + wid * 544;   // 8 cols x 68 floats

#pragma unroll
        for (int nt = 0; nt < 8; nt++) {
#pragma unroll
            for (int mt = 0; mt < 4; mt++) {
                const float* a = acc + (mt * 8 + nt) * 4;
                int r = mt * 16 + (lane >> 2);
                int c = (lane & 3) * 2;
                buf[c * 68 + r]       = a[0];
                buf[(c + 1) * 68 + r] = a[1];
                buf[c * 68 + r + 8]       = a[2];
                buf[(c + 1) * 68 + r + 8] = a[3];
            }
            __syncwarp();
#pragma unroll
            for (int j = 0; j < 16; j++) {
                int idx = j * 32 + lane;
                int ml = idx & 63, c = idx >> 6;
                int n = n0 + wn * 64 + nt * 8 + c;
                int mrow = m0 + wm * 64 + ml;
                float v = sg[wm * 64 + ml] * (buf[c * 68 + ml] + __ldg(&bias[n]));
                int p = mrow & 31, nnp = (mrow >> 5) & 63, bb = mrow >> 11;
                size_t o = (((size_t)bb * Oo + n) * Nn + nnp) * Pp + p;
                if (accflag) v += outp[o];
                outp[o] = v;
            }
            __syncwarp();
        }
    }
}

// ---------------------------------------------------------------------------
// Launcher (graph-capturable: kernel launches only)
// ---------------------------------------------------------------------------
extern "C" void kernel_launch(void* const* d_in, const int* in_sizes, int n_in,
                              void* d_out, int out_size) {
    (void)in_sizes; (void)n_in; (void)out_size;
    const float* x       = (const float*)d_in[0];
    const float* Wg      = (const float*)d_in[1];
    const float* bg      = (const float*)d_in[2];
    const float* Wn      = (const float*)d_in[3];
    const float* bn      = (const float*)d_in[4];
    const float* W1      = (const float*)d_in[5];
    const float* b1      = (const float*)d_in[6];
    const float* W2      = (const float*)d_in[7];
    const float* b2      = (const float*)d_in[8];
    const float* noise_u = (const float*)d_in[9];
    float* out = (float*)d_out;

    cudaFuncSetAttribute(moe_gemm<Cc, Hh, 0>, cudaFuncAttributeMaxDynamicSharedMemorySize, SMEM_T);
    cudaFuncSetAttribute(moe_gemm<Hh, Oo, 1>, cudaFuncAttributeMaxDynamicSharedMemorySize, SMEM_T);

    transpose_kernel<<<dim3(SS / 32, Cc / 32, Bb), dim3(32, 8)>>>(x);
    wsplit_kernel<1><<<dim3(Hh / 32, Cc / 32, Ee), dim3(32, 8)>>>(W1);
    wsplit_kernel<2><<<dim3(Oo / 32, Hh / 32, Ee), dim3(32, 8)>>>(W2);
    router_kernel<<<AT / 8, 256>>>(Wg, bg, Wn, bn, noise_u);

    for (int e = 0; e < Ee; e++) {
        moe_gemm<Cc, Hh, 0><<<dim3(Hh / 256, AT / 128), 256, SMEM_T>>>(
            b1 + (size_t)e * Hh, nullptr, e, 0);
        moe_gemm<Hh, Oo, 1><<<dim3(Oo / 256, AT / 128), 256, SMEM_T>>>(
            b2 + (size_t)e * Oo, out, e, (e > 0) ? 1 : 0);
    }
}